// round 7
// baseline (speedup 1.0000x reference)
#include <cuda_runtime.h>
#include <cstdint>

// ---------------- problem constants ----------------
#define TSEQ   4096
#define EMB    300
#define HID    500
#define HP     512            // padded hidden (cols 500..511 always 0.0, never NaN)
#define GATES  2000           // 4*HID, torch gate order i,f,g,o
#define NCLS   90

// ---------------- persistent-kernel config (proven R2/R6 skeleton) ----------------
#define NB0    50             // layer-0 CTAs, 10 units each (50*10 = 500 exact)
#define U0     10
#define RPW0   5              // rows per warp, layer 0: 40 rows / 8 warps
#define NB1    84             // layer-1 CTAs, 6 units each (84*6 = 504 >= 500)
#define U1     6
#define RPW1   6              // half-rows per warp, layer 1: 48 / 8 warps
#define NBLK   (NB0 + NB1)    // 134 <= 148 SMs -> all co-resident at occupancy 1
#define THREADS 256           // 8 warps

// ---------------- device scratch (static allocation only) ----------------
__device__ float g_xp0[(size_t)TSEQ * GATES];       // precomputed x-projection, layer 0
__device__ float g_h1[(TSEQ + 1) * HP];             // layer-0 hidden seq (row 0 = zeros, never touched)
__device__ float g_h2[(TSEQ + 1) * HP];             // layer-1 hidden seq (row 0 = zeros, never touched)
__device__ float g_Wt[EMB * GATES];                 // W_ih0 transposed: [e][g]

// ---------------- init: NaN-sentinel rows 1..TSEQ (cols<500), pad cols = 0 ----------------
// Self-validating data-as-flag: consumers retry until their OWN x values are not NaN.
// Each 32-bit word is atomically either sentinel or final -> no ordering needed at all.
__global__ void k_init() {
    const size_t nvec = (size_t)TSEQ * (HP / 4);    // uint4 per array, rows 1..TSEQ
    const uint4 nanv  = make_uint4(0x7FC00000u, 0x7FC00000u, 0x7FC00000u, 0x7FC00000u);
    const uint4 zerov = make_uint4(0u, 0u, 0u, 0u);
    uint4* a = reinterpret_cast<uint4*>(g_h1 + HP);
    uint4* b = reinterpret_cast<uint4*>(g_h2 + HP);
    for (size_t i = blockIdx.x * blockDim.x + threadIdx.x; i < 2 * nvec;
         i += (size_t)gridDim.x * blockDim.x) {
        size_t j = (i < nvec) ? i : i - nvec;
        int col4 = (int)(j & (HP / 4 - 1));          // 0..127 (uint4 index within row)
        uint4 v = (col4 < 125) ? nanv : zerov;       // 125*4 = 500 exactly
        if (i < nvec) a[j] = v; else b[j] = v;
    }
}

// ---------------- transpose W_ih0 [2000,300] -> [300,2000] ----------------
__global__ void k_transpose(const float* __restrict__ W) {
    int idx = blockIdx.x * 256 + threadIdx.x;
    if (idx < EMB * GATES) {
        int e = idx / GATES;
        int g = idx % GATES;
        g_Wt[idx] = W[g * EMB + e];
    }
}

// ---------------- x-projection GEMM: xp0[t][g] = emb[seq[t]] . W_ih0[g] + bih0 + bhh0 ----
__global__ void k_xproj(const int* __restrict__ seq,
                        const float* __restrict__ emb,
                        const float* __restrict__ bih0,
                        const float* __restrict__ bhh0) {
    __shared__ __align__(16) float embs[16][304];
    int g  = blockIdx.x * 128 + threadIdx.x;
    int t0 = blockIdx.y * 16;

    for (int idx = threadIdx.x; idx < 16 * 304; idx += 128) {
        int tt = idx / 304, e = idx % 304;
        float v = 0.f;
        if (e < EMB) v = emb[(size_t)seq[t0 + tt] * EMB + e];
        embs[tt][e] = v;
    }
    __syncthreads();

    float acc[16];
    float b = (g < GATES) ? (bih0[g] + bhh0[g]) : 0.f;
#pragma unroll
    for (int tt = 0; tt < 16; tt++) acc[tt] = b;

    for (int e4 = 0; e4 < 75; e4++) {
        float w0 = 0.f, w1 = 0.f, w2 = 0.f, w3 = 0.f;
        if (g < GATES) {
            w0 = g_Wt[(e4 * 4 + 0) * GATES + g];
            w1 = g_Wt[(e4 * 4 + 1) * GATES + g];
            w2 = g_Wt[(e4 * 4 + 2) * GATES + g];
            w3 = g_Wt[(e4 * 4 + 3) * GATES + g];
        }
#pragma unroll
        for (int tt = 0; tt < 16; tt++) {
            float4 ev = *reinterpret_cast<const float4*>(&embs[tt][e4 * 4]);
            acc[tt] = fmaf(ev.x, w0, fmaf(ev.y, w1, fmaf(ev.z, w2, fmaf(ev.w, w3, acc[tt]))));
        }
    }
    if (g < GATES) {
#pragma unroll
        for (int tt = 0; tt < 16; tt++)
            g_xp0[(size_t)(t0 + tt) * GATES + g] = acc[tt];
    }
}

__device__ __forceinline__ float sigf(float x)     { return 1.f / (1.f + __expf(-x)); }
__device__ __forceinline__ float tanhfast(float x) { return 1.f - 2.f / (__expf(2.f * x) + 1.f); }

// Warp-scoped sentinel load: each lane loads its 16 strided x values; retry until
// no lane sees NaN. Detect latency == data-load latency (one L2 round trip).
__device__ __forceinline__ void load_row_valid(const float* __restrict__ hr, int l,
                                               float (&x)[16]) {
    int tries = 0;
    for (;;) {
#pragma unroll
        for (int k = 0; k < 16; k++) x[k] = __ldcg(hr + l + 32 * k);
        float s = 0.f;
#pragma unroll
        for (int k = 0; k < 16; k++) s += x[k];
        if (__ballot_sync(0xffffffffu, s != s) == 0u) break;
        if (++tries > 2) __nanosleep(50);
    }
}

// ---------------- persistent 2-layer LSTM recurrence ----------------
// Sync = NaN-sentinel data-as-flag. No atomics, no fences, no flags, no release/acquire.
__global__ __launch_bounds__(THREADS, 1)
void k_lstm(const float* __restrict__ Whh0,
            const float* __restrict__ Wih1,
            const float* __restrict__ Whh1,
            const float* __restrict__ bih1,
            const float* __restrict__ bhh1) {
    int b   = blockIdx.x;
    int tid = threadIdx.x;
    int w = tid >> 5, l = tid & 31;

    __shared__ float sums[2][48];
    float wreg[6][16];

    if (b < NB0) {
        // ======================= LAYER 0 =======================
        const int ub = b * U0;
#pragma unroll
        for (int j = 0; j < RPW0; j++) {
            int r = w * RPW0 + j;          // 0..39
            int q = r / U0, u = r % U0;
            int grow = q * HID + ub + u;
#pragma unroll
            for (int k = 0; k < 16; k++) {
                int idx = l + 32 * k;
                wreg[j][k] = (idx < HID) ? Whh0[grow * HID + idx] : 0.f;
            }
        }
        float c = 0.f;

        for (int t = 0; t < TSEQ; t++) {
            // xp prefetch (independent data; latency hides under the sentinel wait)
            float xp0v = 0.f, xp1v = 0.f, xp2v = 0.f, xp3v = 0.f;
            if (tid < U0) {
                const float* xp = &g_xp0[(size_t)t * GATES + ub + tid];
                xp0v = __ldcg(xp + 0 * HID);
                xp1v = __ldcg(xp + 1 * HID);
                xp2v = __ldcg(xp + 2 * HID);
                xp3v = __ldcg(xp + 3 * HID);
            }

            // sentinel-validated x load: detect + load in one round trip
            float x[16];
            load_row_valid(&g_h1[(size_t)t * HP], l, x);

            float* sb = sums[t & 1];
#pragma unroll
            for (int j = 0; j < RPW0; j++) {
                float acc = 0.f;
#pragma unroll
                for (int k = 0; k < 16; k++) acc = fmaf(wreg[j][k], x[k], acc);
#pragma unroll
                for (int off = 16; off; off >>= 1)
                    acc += __shfl_xor_sync(0xffffffffu, acc, off);
                if (l == 0) sb[w * RPW0 + j] = acc;
            }
            __syncthreads();

            if (w == 0 && l < U0) {
                float pi = sb[0 * U0 + l] + xp0v;
                float pf = sb[1 * U0 + l] + xp1v;
                float pg = sb[2 * U0 + l] + xp2v;
                float po = sb[3 * U0 + l] + xp3v;
                float ig = sigf(pi), fg = sigf(pf), og = sigf(po);
                float gg = tanhfast(pg);
                c = fg * c + ig * gg;
                float h = og * tanhfast(c);
                __stcg(&g_h1[(size_t)(t + 1) * HP + ub + l], h);
            }
        }
    } else {
        // ======================= LAYER 1 =======================
        const int bb = b - NB0;
        const int ub = bb * U1;
#pragma unroll
        for (int j = 0; j < RPW1; j++) {
            int hr = w * RPW1 + j;         // 0..47; [0,24)=W_ih1 (x=h1), [24,48)=W_hh1 (x=h2)
            int rl = hr % 24;
            int q = rl / U1, u = rl % U1;
            int ug = ub + u;
            int grow = q * HID + ug;
            const float* W = (hr >= 24) ? Whh1 : Wih1;
#pragma unroll
            for (int k = 0; k < 16; k++) {
                int idx = l + 32 * k;
                wreg[j][k] = (ug < HID && idx < HID) ? W[grow * HID + idx] : 0.f;
            }
        }
        float bg0 = 0.f, bg1 = 0.f, bg2 = 0.f, bg3 = 0.f, c = 0.f;
        if (tid < U1 && (ub + tid) < HID) {
            int base = ub + tid;
            bg0 = bih1[0 * HID + base] + bhh1[0 * HID + base];
            bg1 = bih1[1 * HID + base] + bhh1[1 * HID + base];
            bg2 = bih1[2 * HID + base] + bhh1[2 * HID + base];
            bg3 = bih1[3 * HID + base] + bhh1[3 * HID + base];
        }

        for (int t = 0; t < TSEQ; t++) {
            // warps 0-3 wait only on h1(t) (= g_h1 row t+1); warps 4-7 only on h2(t-1)
            const float* xs = (w < 4) ? &g_h1[(size_t)(t + 1) * HP]
                                      : &g_h2[(size_t)t * HP];
            float x[16];
            load_row_valid(xs, l, x);

            float* sb = sums[t & 1];
#pragma unroll
            for (int j = 0; j < RPW1; j++) {
                float acc = 0.f;
#pragma unroll
                for (int k = 0; k < 16; k++) acc = fmaf(wreg[j][k], x[k], acc);
#pragma unroll
                for (int off = 16; off; off >>= 1)
                    acc += __shfl_xor_sync(0xffffffffu, acc, off);
                if (l == 0) sb[w * RPW1 + j] = acc;
            }
            __syncthreads();

            if (w == 0 && l < U1) {
                float pi = sb[0 * U1 + l] + sb[24 + 0 * U1 + l] + bg0;
                float pf = sb[1 * U1 + l] + sb[24 + 1 * U1 + l] + bg1;
                float pg = sb[2 * U1 + l] + sb[24 + 2 * U1 + l] + bg2;
                float po = sb[3 * U1 + l] + sb[24 + 3 * U1 + l] + bg3;
                float ig = sigf(pi), fg = sigf(pf), og = sigf(po);
                float gg = tanhfast(pg);
                c = fg * c + ig * gg;
                float h = og * tanhfast(c);
                if ((ub + l) < HID)
                    __stcg(&g_h2[(size_t)(t + 1) * HP + ub + l], h);
            }
        }
    }
}

// ---------------- final FC: out = h2[last] @ fc_W^T + fc_b ----------------
__global__ void k_fc(const float* __restrict__ fcW,
                     const float* __restrict__ fcb,
                     float* __restrict__ out) {
    int b = blockIdx.x;        // class
    int l = threadIdx.x;       // lane
    float acc = 0.f;
    for (int k = l; k < HID; k += 32)
        acc += fcW[b * HID + k] * g_h2[TSEQ * HP + k];
#pragma unroll
    for (int off = 16; off; off >>= 1)
        acc += __shfl_xor_sync(0xffffffffu, acc, off);
    if (l == 0) out[b] = acc + fcb[b];
}

// ---------------- launch ----------------
extern "C" void kernel_launch(void* const* d_in, const int* in_sizes, int n_in,
                              void* d_out, int out_size) {
    const int*   seq  = (const int*)  d_in[0];
    const float* emb  = (const float*)d_in[1];
    const float* Wih0 = (const float*)d_in[2];
    const float* Whh0 = (const float*)d_in[3];
    const float* bih0 = (const float*)d_in[4];
    const float* bhh0 = (const float*)d_in[5];
    const float* Wih1 = (const float*)d_in[6];
    const float* Whh1 = (const float*)d_in[7];
    const float* bih1 = (const float*)d_in[8];
    const float* bhh1 = (const float*)d_in[9];
    const float* fcW  = (const float*)d_in[10];
    const float* fcb  = (const float*)d_in[11];

    k_init<<<148, 256>>>();
    k_transpose<<<(EMB * GATES + 255) / 256, 256>>>(Wih0);
    dim3 gx(16, 256);
    k_xproj<<<gx, 128>>>(seq, emb, bih0, bhh0);
    k_lstm<<<NBLK, THREADS>>>(Whh0, Wih1, Whh1, bih1, bhh1);
    k_fc<<<NCLS, 32>>>(fcW, fcb, (float*)d_out);
}

// round 8
// speedup vs baseline: 1.9511x; 1.9511x over previous
#include <cuda_runtime.h>
#include <cstdint>

// ---------------- problem constants ----------------
#define TSEQ   4096
#define EMB    300
#define HID    500
#define HP     512            // padded hidden (pad 500..511 never written -> stays 0)
#define GATES  2000           // 4*HID, torch gate order i,f,g,o
#define NCLS   90

// ---------------- persistent-kernel config ----------------
// CTAs [0,50): layer-0 recurrence (10 units each, 40 rows, dot=500)
// CTAs [50,92): layer-1 recurrence (12 units each, 48 hh-rows, dot=500)
// CTAs [92,134): layer-1 input-projection helpers (48 gate-rows each, dot=500)
#define NB0    50
#define U0     10
#define RPW0   5              // 40 rows / 8 warps
#define NB1    42
#define U1     12
#define RPW1   6              // 48 rows / 8 warps
#define NH     42
#define HRPW   6              // 48 rows / 8 warps
#define NBLK   (NB0 + NB1 + NH)   // 134 <= 148 -> all co-resident
#define THREADS 256

#define NGRP   8
// quotas: 50 = 2*7 + 6*6 ; 42 = 2*6 + 6*5
__device__ __forceinline__ int quota50(int g) { return (g < 2) ? 7 : 6; }
__device__ __forceinline__ int quota42(int g) { return (g < 2) ? 6 : 5; }

#define XP1S   2048           // xp1 row stride (2016 rows of data, padded)

// ---------------- device scratch ----------------
__device__ float g_xp0[(size_t)TSEQ * GATES];       // layer-0 input projection (precomputed)
__device__ float g_xp1[(size_t)(TSEQ + 1) * XP1S];  // layer-1 input projection (pipelined): [r][unit*4+gate]
__device__ float g_h1[(TSEQ + 1) * HP];             // layer-0 hidden (row 0 = zeros)
__device__ float g_h2[(TSEQ + 1) * HP];             // layer-1 hidden (row 0 = zeros)
__device__ int   g_c1[(TSEQ + 1) * NGRP];           // h1 row-ready counters (50 producers)
__device__ int   g_c2[(TSEQ + 1) * NGRP];           // h2 row-ready counters (42 producers)
__device__ int   g_c3[(TSEQ + 1) * NGRP];           // xp1 row-ready counters (42 producers)
__device__ float g_Wt[EMB * GATES];                 // W_ih0 transposed

// ---------------- acquire/release primitives ----------------
__device__ __forceinline__ int ld_acq(const int* p) {
    int v;
    asm volatile("ld.acquire.gpu.global.b32 %0, [%1];" : "=r"(v) : "l"(p) : "memory");
    return v;
}
__device__ __forceinline__ void red_release(int* p) {
    asm volatile("red.release.gpu.global.add.u32 [%0], 1;" :: "l"(p) : "memory");
}

// ---------------- init: reset counters every replay ----------------
__global__ void k_init() {
    const int n = (TSEQ + 1) * NGRP;
    for (int i = blockIdx.x * blockDim.x + threadIdx.x; i < 3 * n;
         i += gridDim.x * blockDim.x) {
        int which = i / n, j = i % n, g = j % NGRP;
        int v;
        if (j >= NGRP) v = 0;
        else v = (which == 0) ? quota50(g) : quota42(g);   // row 0 = ready
        if (which == 0) g_c1[j] = v;
        else if (which == 1) g_c2[j] = v;
        else g_c3[j] = v;
    }
}

// ---------------- transpose W_ih0 [2000,300] -> [300,2000] ----------------
__global__ void k_transpose(const float* __restrict__ W) {
    int idx = blockIdx.x * 256 + threadIdx.x;
    if (idx < EMB * GATES) {
        int e = idx / GATES;
        int g = idx % GATES;
        g_Wt[idx] = W[g * EMB + e];
    }
}

// ---------------- x-projection GEMM for layer 0 (precomputed, time-parallel) ----------
__global__ void k_xproj(const int* __restrict__ seq,
                        const float* __restrict__ emb,
                        const float* __restrict__ bih0,
                        const float* __restrict__ bhh0) {
    __shared__ __align__(16) float embs[16][304];
    int g  = blockIdx.x * 128 + threadIdx.x;
    int t0 = blockIdx.y * 16;

    for (int idx = threadIdx.x; idx < 16 * 304; idx += 128) {
        int tt = idx / 304, e = idx % 304;
        float v = 0.f;
        if (e < EMB) v = emb[(size_t)seq[t0 + tt] * EMB + e];
        embs[tt][e] = v;
    }
    __syncthreads();

    float acc[16];
    float b = (g < GATES) ? (bih0[g] + bhh0[g]) : 0.f;
#pragma unroll
    for (int tt = 0; tt < 16; tt++) acc[tt] = b;

    for (int e4 = 0; e4 < 75; e4++) {
        float w0 = 0.f, w1 = 0.f, w2 = 0.f, w3 = 0.f;
        if (g < GATES) {
            w0 = g_Wt[(e4 * 4 + 0) * GATES + g];
            w1 = g_Wt[(e4 * 4 + 1) * GATES + g];
            w2 = g_Wt[(e4 * 4 + 2) * GATES + g];
            w3 = g_Wt[(e4 * 4 + 3) * GATES + g];
        }
#pragma unroll
        for (int tt = 0; tt < 16; tt++) {
            float4 ev = *reinterpret_cast<const float4*>(&embs[tt][e4 * 4]);
            acc[tt] = fmaf(ev.x, w0, fmaf(ev.y, w1, fmaf(ev.z, w2, fmaf(ev.w, w3, acc[tt]))));
        }
    }
    if (g < GATES) {
#pragma unroll
        for (int tt = 0; tt < 16; tt++)
            g_xp0[(size_t)(t0 + tt) * GATES + g] = acc[tt];
    }
}

__device__ __forceinline__ float sigf(float x)     { return 1.f / (1.f + __expf(-x)); }
__device__ __forceinline__ float tanhfast(float x) { return 1.f - 2.f / (__expf(2.f * x) + 1.f); }

// ---------------- persistent pipelined LSTM ----------------
__global__ __launch_bounds__(THREADS, 1)
void k_lstm(const float* __restrict__ Whh0,
            const float* __restrict__ Wih1,
            const float* __restrict__ Whh1,
            const float* __restrict__ bih1,
            const float* __restrict__ bhh1) {
    int b   = blockIdx.x;
    int tid = threadIdx.x;
    int w = tid >> 5, l = tid & 31;

    __shared__ float sums[2][48];
    float wreg[6][16];

    if (b < NB0) {
        // ============ LAYER 0 recurrence (unchanged R6 skeleton) ============
        const int ub = b * U0;
        const int grp = b & 7;
#pragma unroll
        for (int j = 0; j < RPW0; j++) {
            int r = w * RPW0 + j;
            int q = r / U0, u = r % U0;
            int grow = q * HID + ub + u;
#pragma unroll
            for (int k = 0; k < 16; k++) {
                int idx = l + 32 * k;
                wreg[j][k] = (idx < HID) ? Whh0[grow * HID + idx] : 0.f;
            }
        }
        float c = 0.f;
        const int need = (l < NGRP) ? quota50(l) : 0;

        for (int t = 0; t < TSEQ; t++) {
            float xp0v = 0.f, xp1v = 0.f, xp2v = 0.f, xp3v = 0.f;
            if (tid < U0) {
                const float* xp = &g_xp0[(size_t)t * GATES + ub + tid];
                xp0v = __ldcg(xp + 0 * HID);
                xp1v = __ldcg(xp + 1 * HID);
                xp2v = __ldcg(xp + 2 * HID);
                xp3v = __ldcg(xp + 3 * HID);
            }
            {
                const int* cp = &g_c1[t * NGRP + (l & 7)];
                for (;;) {
                    int v = (l < NGRP) ? ld_acq(cp) : 0;
                    if (__all_sync(0xffffffffu, v >= need)) break;
                }
                __syncwarp();
            }
            const float* hr = &g_h1[(size_t)t * HP];
            float x[16];
#pragma unroll
            for (int k = 0; k < 16; k++) x[k] = __ldcg(hr + l + 32 * k);

            float* sb = sums[t & 1];
#pragma unroll
            for (int j = 0; j < RPW0; j++) {
                float acc = 0.f;
#pragma unroll
                for (int k = 0; k < 16; k++) acc = fmaf(wreg[j][k], x[k], acc);
#pragma unroll
                for (int off = 16; off; off >>= 1)
                    acc += __shfl_xor_sync(0xffffffffu, acc, off);
                if (l == 0) sb[w * RPW0 + j] = acc;
            }
            __syncthreads();

            if (w == 0) {
                if (l < U0) {
                    float pi = sb[0 * U0 + l] + xp0v;
                    float pf = sb[1 * U0 + l] + xp1v;
                    float pg = sb[2 * U0 + l] + xp2v;
                    float po = sb[3 * U0 + l] + xp3v;
                    float ig = sigf(pi), fg = sigf(pf), og = sigf(po);
                    float gg = tanhfast(pg);
                    c = fg * c + ig * gg;
                    __stcg(&g_h1[(size_t)(t + 1) * HP + ub + l], og * tanhfast(c));
                }
                __syncwarp();
                if (l == 0) red_release(&g_c1[(t + 1) * NGRP + grp]);
            }
        }
    } else if (b < NB0 + NB1) {
        // ============ LAYER 1 recurrence: ONLY W_hh1 (thin chain) ============
        const int bb = b - NB0;
        const int ub = bb * U1;                 // units ub..ub+11 (pad >= 500)
        const int grp = bb & 7;
        // local row rr = ulocal*4 + q ; warp w owns rr = w*6..w*6+5
#pragma unroll
        for (int j = 0; j < RPW1; j++) {
            int rr = w * RPW1 + j;
            int ul = rr >> 2, q = rr & 3;
            int u = ub + ul;
            const float* Wr = Whh1 + (size_t)(q * HID + (u < HID ? u : 0)) * HID;
#pragma unroll
            for (int k = 0; k < 16; k++) {
                int idx = l + 32 * k;
                wreg[j][k] = (u < HID && idx < HID) ? Wr[idx] : 0.f;
            }
        }
        float c = 0.f;
        // lanes 0-7: xp1 counters (42 producers), lanes 8-15: h2 counters (42)
        const int need = (l < 2 * NGRP) ? quota42(l & 7) : 0;

        for (int t = 0; t < TSEQ; t++) {
            {
                const int* cp3 = &g_c3[(t + 1) * NGRP + (l & 7)];
                const int* cp2 = &g_c2[t * NGRP + (l & 7)];
                for (;;) {
                    int v = (l < NGRP) ? ld_acq(cp3)
                          : (l < 2 * NGRP) ? ld_acq(cp2) : 0;
                    if (__all_sync(0xffffffffu, v >= need)) break;
                }
                __syncwarp();
            }
            // gate lanes fetch xp1 (just published) while all lanes fetch h2 row
            float4 xp = make_float4(0.f, 0.f, 0.f, 0.f);
            if (w == 0 && l < U1)
                xp = *reinterpret_cast<const float4*>(
                        &g_xp1[(size_t)(t + 1) * XP1S + (ub + l) * 4]);

            const float* hr = &g_h2[(size_t)t * HP];
            float x[16];
#pragma unroll
            for (int k = 0; k < 16; k++) x[k] = __ldcg(hr + l + 32 * k);

            float* sb = sums[t & 1];
#pragma unroll
            for (int j = 0; j < RPW1; j++) {
                float acc = 0.f;
#pragma unroll
                for (int k = 0; k < 16; k++) acc = fmaf(wreg[j][k], x[k], acc);
#pragma unroll
                for (int off = 16; off; off >>= 1)
                    acc += __shfl_xor_sync(0xffffffffu, acc, off);
                if (l == 0) sb[w * RPW1 + j] = acc;
            }
            __syncthreads();

            if (w == 0) {
                if (l < U1) {
                    float pi = sb[l * 4 + 0] + xp.x;
                    float pf = sb[l * 4 + 1] + xp.y;
                    float pg = sb[l * 4 + 2] + xp.z;
                    float po = sb[l * 4 + 3] + xp.w;
                    float ig = sigf(pi), fg = sigf(pf), og = sigf(po);
                    float gg = tanhfast(pg);
                    c = fg * c + ig * gg;
                    if ((ub + l) < HID)
                        __stcg(&g_h2[(size_t)(t + 1) * HP + ub + l], og * tanhfast(c));
                }
                __syncwarp();
                if (l == 0) red_release(&g_c2[(t + 1) * NGRP + grp]);
            }
        }
    } else {
        // ============ HELPERS: xp1[r] = W_ih1 @ h1[r] + biases (pipelined) ============
        const int hh = b - NB0 - NB1;           // 0..41
        const int R0 = hh * 48;                 // global rows R0..R0+47 ; row r: unit r>>2, gate r&3
        const int grp = hh & 7;
        float brow[HRPW];
#pragma unroll
        for (int j = 0; j < HRPW; j++) {
            int r = R0 + w * HRPW + j;
            int u = r >> 2, q = r & 3;
            const float* Wr = Wih1 + (size_t)(q * HID + (u < HID ? u : 0)) * HID;
#pragma unroll
            for (int k = 0; k < 16; k++) {
                int idx = l + 32 * k;
                wreg[j][k] = (u < HID && idx < HID) ? Wr[idx] : 0.f;
            }
            brow[j] = (u < HID) ? (bih1[q * HID + u] + bhh1[q * HID + u]) : 0.f;
        }
        const int need = (l < NGRP) ? quota50(l) : 0;

        for (int t = 0; t < TSEQ; t++) {
            {
                const int* cp = &g_c1[(t + 1) * NGRP + (l & 7)];
                for (;;) {
                    int v = (l < NGRP) ? ld_acq(cp) : 0;
                    if (__all_sync(0xffffffffu, v >= need)) break;
                }
                __syncwarp();
            }
            const float* hr = &g_h1[(size_t)(t + 1) * HP];
            float x[16];
#pragma unroll
            for (int k = 0; k < 16; k++) x[k] = __ldcg(hr + l + 32 * k);

#pragma unroll
            for (int j = 0; j < HRPW; j++) {
                float acc = 0.f;
#pragma unroll
                for (int k = 0; k < 16; k++) acc = fmaf(wreg[j][k], x[k], acc);
#pragma unroll
                for (int off = 16; off; off >>= 1)
                    acc += __shfl_xor_sync(0xffffffffu, acc, off);
                if (l == 0)
                    __stcg(&g_xp1[(size_t)(t + 1) * XP1S + R0 + w * HRPW + j],
                           acc + brow[j]);
            }
            __syncthreads();          // all 8 warps' stores issued before release
            if (tid == 0) red_release(&g_c3[(t + 1) * NGRP + grp]);
        }
    }
}

// ---------------- final FC: out = h2[last] @ fc_W^T + fc_b ----------------
__global__ void k_fc(const float* __restrict__ fcW,
                     const float* __restrict__ fcb,
                     float* __restrict__ out) {
    int b = blockIdx.x;
    int l = threadIdx.x;
    float acc = 0.f;
    for (int k = l; k < HID; k += 32)
        acc += fcW[b * HID + k] * g_h2[TSEQ * HP + k];
#pragma unroll
    for (int off = 16; off; off >>= 1)
        acc += __shfl_xor_sync(0xffffffffu, acc, off);
    if (l == 0) out[b] = acc + fcb[b];
}

// ---------------- launch ----------------
extern "C" void kernel_launch(void* const* d_in, const int* in_sizes, int n_in,
                              void* d_out, int out_size) {
    const int*   seq  = (const int*)  d_in[0];
    const float* emb  = (const float*)d_in[1];
    const float* Wih0 = (const float*)d_in[2];
    const float* Whh0 = (const float*)d_in[3];
    const float* bih0 = (const float*)d_in[4];
    const float* bhh0 = (const float*)d_in[5];
    const float* Wih1 = (const float*)d_in[6];
    const float* Whh1 = (const float*)d_in[7];
    const float* bih1 = (const float*)d_in[8];
    const float* bhh1 = (const float*)d_in[9];
    const float* fcW  = (const float*)d_in[10];
    const float* fcb  = (const float*)d_in[11];

    k_init<<<64, 256>>>();
    k_transpose<<<(EMB * GATES + 255) / 256, 256>>>(Wih0);
    dim3 gx(16, 256);
    k_xproj<<<gx, 128>>>(seq, emb, bih0, bhh0);
    k_lstm<<<NBLK, THREADS>>>(Whh0, Wih1, Whh1, bih1, bhh1);
    k_fc<<<NCLS, 32>>>(fcW, fcb, (float*)d_out);
}